// round 5
// baseline (speedup 1.0000x reference)
#include <cuda_runtime.h>
#include <cuda_fp16.h>

// Problem constants
#define VSZ   30000
#define OC    128
#define KW    5
#define BATCH 32

constexpr int L    = 2560;          // 40*64 flattened token positions per batch
constexpr int LOUT = L - KW + 1;    // 2556
constexpr int CW   = VSZ * KW;      // 150000 columns of the K matrix (v*5+w)
constexpr int NSUB = 128;           // sub-chunks of the l-range
constexpr int SUBL = 20;            // 128*20 = 2560 >= LOUT

// Scratch: transposed fp16 table Kt[v][w][oc]  (38.4 MB, L2-resident)
__device__ __align__(16) __half g_Kt[(size_t)VSZ * KW * OC];
// Per-warp partial maxima: [b][sub][oc]
__device__ float g_partial[BATCH][NSUB][OC];

// ---------------------------------------------------------------------------
// Kernel 1: transpose + fp32->fp16 convert.
// K is (128 x 150000), row = oc, col = v*5+w.  ->  Kt[col][oc] as half.
// One block = 64 columns x all 128 oc; float2 source loads (halved request
// count), coalesced 256B Kt-row writes. Source reads __ldcs (evict-first)
// so L2 keeps Kt resident for the conv.
// ---------------------------------------------------------------------------
__global__ void __launch_bounds__(256) transpose_kernel(const float* __restrict__ src) {
    __shared__ __half tile[64][130];          // [col-local][oc]
    const int tx = threadIdx.x & 31;          // float2-column within tile
    const int ty = threadIdx.x >> 5;          // 0..7
    const int cbase = blockIdx.x * 64;
    const int c2 = cbase + tx * 2;            // even global column
    const bool cok = (c2 < CW);               // CW even -> c2+1 also in range

    #pragma unroll
    for (int i = 0; i < 16; i++) {
        int r = ty + i * 8;                   // oc 0..127
        if (cok) {
            float2 v = __ldcs(reinterpret_cast<const float2*>(src + (size_t)r * CW + cbase) + tx);
            tile[tx * 2    ][r] = __float2half(v.x);
            tile[tx * 2 + 1][r] = __float2half(v.y);
        }
    }
    __syncthreads();

    // Write out: 64 rows x 64 uints (128 halfs) each, 16/thread.
    const int colu  = threadIdx.x & 63;       // uint index within a Kt row
    const int rbase = threadIdx.x >> 6;       // 0..3
    #pragma unroll
    for (int i = 0; i < 16; i++) {
        int row = rbase + i * 4;              // col-local 0..63
        int vw  = cbase + row;
        if (vw < CW) {
            const unsigned* srow = reinterpret_cast<const unsigned*>(&tile[row][0]);
            reinterpret_cast<unsigned*>(g_Kt)[(size_t)vw * 64 + colu] = srow[colu];
        }
    }
}

// ---------------------------------------------------------------------------
// Kernel 2: gather + sliding-window conv + relu-max
// grid = (NSUB/4, BATCH), block = 256 (8 warps); 2 warps per sub-chunk,
// each covering 64 oc via half2 lanes, fp32 accumulate.
// Ids for the whole sub-chunk (<=24) are preloaded with ONE lane-parallel
// load and broadcast via __shfl.
// CRITICAL: the ring-slot reset acc[(j+1)%5] = 0 must run UNCONDITIONALLY
// every iteration — at j=0..3 it flushes boundary pollution (w>j terms that
// belong to the previous sub-chunk's conv positions) before that slot's
// valid accumulation begins. Only the max is guarded by j>=4.
// ---------------------------------------------------------------------------
__device__ __forceinline__ void addh(float2& a, const half2 b) {
    float2 f = __half22float2(b);
    a.x += f.x; a.y += f.y;
}
__device__ __forceinline__ void max2(float2& a, const float2 b) {
    a.x = fmaxf(a.x, b.x); a.y = fmaxf(a.y, b.y);
}

__global__ void __launch_bounds__(256) conv_kernel(const int* __restrict__ tokens) {
    const int b    = blockIdx.y;
    const int warp = threadIdx.x >> 5;
    const int lane = threadIdx.x & 31;
    const int sub  = blockIdx.x * 4 + (warp >> 1);
    const int half = warp & 1;
    const int off  = half * 32 + lane;   // half2 index into the 128-oc row

    const int l0 = sub * SUBL;
    const int l1 = min(l0 + SUBL, LOUT);
    const int n  = l1 + KW - 1 - l0;     // tokens this sub-chunk (<= 24)

    const int* ids = tokens + b * L;
    // One lane-parallel load covers all ids for this sub-chunk.
    int myid = 0;
    if (lane < n) myid = __ldg(ids + l0 + lane);

    const half2* __restrict__ Kt2 = reinterpret_cast<const half2*>(g_Kt);

    float2 acc[5];
    #pragma unroll
    for (int i = 0; i < 5; i++) acc[i] = make_float2(0.f, 0.f);
    float2 vmax = make_float2(0.f, 0.f);   // relu: floor at 0

    #pragma unroll
    for (int j = 0; j < SUBL + KW - 1; j++) {       // j = p - l0
        if (j < n) {
            int id = __shfl_sync(0xFFFFFFFFu, myid, j);
            const half2* srcp = Kt2 + (size_t)id * (KW * 64) + off;
            half2 v0 = __ldg(srcp +   0);
            half2 v1 = __ldg(srcp +  64);
            half2 v2 = __ldg(srcp + 128);
            half2 v3 = __ldg(srcp + 192);
            half2 v4 = __ldg(srcp + 256);
            // conv[l = p - w] += K[:, id, w]; slot(l) = (l - l0) mod 5
            addh(acc[(j + 5 - 0) % 5], v0);
            addh(acc[(j + 5 - 1) % 5], v1);
            addh(acc[(j + 5 - 2) % 5], v2);
            addh(acc[(j + 5 - 3) % 5], v3);
            addh(acc[(j + 5 - 4) % 5], v4);
            // slot (j+1)%5: completed conv[p-4] when j>=4; stale boundary
            // pollution when j<4 — reset it either way.
            const int s = (j + 1) % 5;
            if (j >= 4) max2(vmax, acc[s]);
            acc[s] = make_float2(0.f, 0.f);
        }
    }
    float2* dst = reinterpret_cast<float2*>(&g_partial[b][sub][0]);
    dst[off] = vmax;
}

// ---------------------------------------------------------------------------
// Kernel 3: reduce sub-chunk maxima + tiny FC.  grid = 32 (b), block = 128.
// ---------------------------------------------------------------------------
__global__ void __launch_bounds__(128) final_kernel(const float* __restrict__ fc1_w,
                                                    const float* __restrict__ fc1_b,
                                                    float* __restrict__ out) {
    const int b  = blockIdx.x;
    const int t  = threadIdx.x;          // = oc
    const int warp = t >> 5, lane = t & 31;

    const float* part = &g_partial[b][0][0]; // [NSUB][128]
    float pooled = 0.f;
    #pragma unroll 8
    for (int s = 0; s < NSUB; s++)
        pooled = fmaxf(pooled, part[s * OC + t]);

    __shared__ float shw[4][4];          // [warp][tc]
    #pragma unroll
    for (int tc = 0; tc < 4; tc++) {
        float v = pooled * fc1_w[tc * OC + t];
        #pragma unroll
        for (int off = 16; off > 0; off >>= 1)
            v += __shfl_down_sync(0xFFFFFFFFu, v, off);
        if (lane == 0) shw[warp][tc] = v;
    }
    __syncthreads();
    if (t < 4) {
        float s = shw[0][t] + shw[1][t] + shw[2][t] + shw[3][t];
        out[b * 4 + t] = s + fc1_b[t];
    }
}

// ---------------------------------------------------------------------------
extern "C" void kernel_launch(void* const* d_in, const int* in_sizes, int n_in,
                              void* d_out, int out_size) {
    const int*   tokens = (const int*)  d_in[0];
    const float* k1     = (const float*)d_in[1];
    const float* fc1w   = (const float*)d_in[2];
    const float* fc1b   = (const float*)d_in[3];
    float*       out    = (float*)d_out;

    transpose_kernel<<<(CW + 63) / 64, 256>>>(k1);     // 2344 blocks

    conv_kernel<<<dim3(NSUB / 4, BATCH), 256>>>(tokens);

    final_kernel<<<BATCH, 128>>>(fc1w, fc1b, out);
}

// round 6
// speedup vs baseline: 1.0679x; 1.0679x over previous
#include <cuda_runtime.h>
#include <cuda_fp16.h>

// Problem constants
#define VSZ   30000
#define OC    128
#define KW    5
#define BATCH 32

constexpr int L    = 2560;          // 40*64 flattened token positions per batch
constexpr int LOUT = L - KW + 1;    // 2556
constexpr int CW   = VSZ * KW;      // 150000 columns of the K matrix (v*5+w)
constexpr int NSUB = 128;           // sub-chunks of the l-range
constexpr int SUBL = 20;            // 128*20 = 2560 >= LOUT

// Scratch: transposed fp16 table Kt[v][w][oc]  (38.4 MB, L2-resident)
__device__ __align__(16) __half g_Kt[(size_t)VSZ * KW * OC];
// Per-warp partial maxima: [b][sub][oc]
__device__ float g_partial[BATCH][NSUB][OC];

// ---------------------------------------------------------------------------
// Kernel 1: transpose + fp32->fp16 convert.
// K is (128 x 150000), row = oc, col = v*5+w.  ->  Kt[col][oc] as half.
// One block = 64 columns x 128 oc. Each thread loads two vertically-adjacent
// fp32 values (rows r,r+1 of one column), packs to half2, stores ONE uint to
// tile[col][r/2]. tile is uint[64][65]: stride 65 == 1 (mod 32) -> bank-
// conflict-free on both sides. Write-out: full contiguous 256B Kt rows.
// ---------------------------------------------------------------------------
__global__ void __launch_bounds__(256) transpose_kernel(const float* __restrict__ src) {
    __shared__ unsigned tile[64][65];         // [col-local][oc-pair]
    const int clocal = threadIdx.x & 63;      // column within tile
    const int rgrp   = threadIdx.x >> 6;      // 0..3
    const int cbase  = blockIdx.x * 64;
    const int c      = cbase + clocal;        // global column (v*5+w)
    const bool cok   = (c < CW);

    #pragma unroll
    for (int i = 0; i < 16; i++) {
        int rpair = rgrp + i * 4;             // 0..63
        int r = rpair * 2;                    // oc row (even)
        if (cok) {
            float a = __ldcs(src + (size_t) r      * CW + c);
            float b = __ldcs(src + (size_t)(r + 1) * CW + c);
            half2 h = __floats2half2_rn(a, b);   // .x = oc r, .y = oc r+1
            tile[clocal][rpair] = *reinterpret_cast<unsigned*>(&h);
        }
    }
    __syncthreads();

    // Write out: 64 Kt rows x 64 uints (128 halfs) each; 4 rows per pass.
    const int colu = clocal;                  // uint index within a Kt row
    #pragma unroll
    for (int i = 0; i < 16; i++) {
        int row = rgrp + i * 4;               // col-local 0..63
        int vw  = cbase + row;
        if (vw < CW)
            reinterpret_cast<unsigned*>(g_Kt)[(size_t)vw * 64 + colu] = tile[row][colu];
    }
}

// ---------------------------------------------------------------------------
// Kernel 2: gather + sliding-window conv + relu-max
// grid = (NSUB/8, BATCH), block = 256 (8 warps); ONE warp per sub-chunk.
// Each lane owns 4 consecutive oc and loads them as one uint2 (8B) per w
// -> 5 x 256B L2 requests per token (half the request count of the
// 2-warp/half2 version at identical bytes).
// Ids for the whole sub-chunk (<=24) preloaded lane-parallel + __shfl.
// Ring-slot reset MUST be unconditional (boundary-pollution flush, see R3).
// ---------------------------------------------------------------------------
__device__ __forceinline__ void addh4(float4& a, const uint2 v) {
    const half2 h0 = *reinterpret_cast<const half2*>(&v.x);
    const half2 h1 = *reinterpret_cast<const half2*>(&v.y);
    float2 f0 = __half22float2(h0);
    float2 f1 = __half22float2(h1);
    a.x += f0.x; a.y += f0.y; a.z += f1.x; a.w += f1.y;
}
__device__ __forceinline__ void max4(float4& a, const float4 b) {
    a.x = fmaxf(a.x, b.x); a.y = fmaxf(a.y, b.y);
    a.z = fmaxf(a.z, b.z); a.w = fmaxf(a.w, b.w);
}

__global__ void __launch_bounds__(256) conv_kernel(const int* __restrict__ tokens) {
    const int b    = blockIdx.y;
    const int warp = threadIdx.x >> 5;
    const int lane = threadIdx.x & 31;
    const int sub  = blockIdx.x * 8 + warp;

    const int l0 = sub * SUBL;
    const int l1 = min(l0 + SUBL, LOUT);
    const int n  = l1 + KW - 1 - l0;     // tokens this sub-chunk (<= 24)

    const int* ids = tokens + b * L;
    int myid = 0;
    if (lane < n) myid = __ldg(ids + l0 + lane);

    const uint2* __restrict__ Kt8 = reinterpret_cast<const uint2*>(g_Kt);

    float4 acc[5];
    #pragma unroll
    for (int i = 0; i < 5; i++) acc[i] = make_float4(0.f, 0.f, 0.f, 0.f);
    float4 vmax = make_float4(0.f, 0.f, 0.f, 0.f);   // relu: floor at 0

    #pragma unroll
    for (int j = 0; j < SUBL + KW - 1; j++) {       // j = p - l0
        if (j < n) {
            int id = __shfl_sync(0xFFFFFFFFu, myid, j);
            // 640 halfs per token row = 160 uint2; w-row = 32 uint2.
            const uint2* srcp = Kt8 + (size_t)id * 160 + lane;
            uint2 v0 = __ldg(srcp +   0);
            uint2 v1 = __ldg(srcp +  32);
            uint2 v2 = __ldg(srcp +  64);
            uint2 v3 = __ldg(srcp +  96);
            uint2 v4 = __ldg(srcp + 128);
            // conv[l = p - w] += K[:, id, w]; slot(l) = (l - l0) mod 5
            addh4(acc[(j + 5 - 0) % 5], v0);
            addh4(acc[(j + 5 - 1) % 5], v1);
            addh4(acc[(j + 5 - 2) % 5], v2);
            addh4(acc[(j + 5 - 3) % 5], v3);
            addh4(acc[(j + 5 - 4) % 5], v4);
            // slot (j+1)%5: completed conv[p-4] when j>=4; stale boundary
            // pollution when j<4 — reset it either way.
            const int s = (j + 1) % 5;
            if (j >= 4) max4(vmax, acc[s]);
            acc[s] = make_float4(0.f, 0.f, 0.f, 0.f);
        }
    }
    float4* dst = reinterpret_cast<float4*>(&g_partial[b][sub][0]);
    dst[lane] = vmax;
}

// ---------------------------------------------------------------------------
// Kernel 3: reduce sub-chunk maxima + tiny FC.  grid = 32 (b), block = 128.
// ---------------------------------------------------------------------------
__global__ void __launch_bounds__(128) final_kernel(const float* __restrict__ fc1_w,
                                                    const float* __restrict__ fc1_b,
                                                    float* __restrict__ out) {
    const int b  = blockIdx.x;
    const int t  = threadIdx.x;          // = oc
    const int warp = t >> 5, lane = t & 31;

    const float* part = &g_partial[b][0][0]; // [NSUB][128]
    float pooled = 0.f;
    #pragma unroll 8
    for (int s = 0; s < NSUB; s++)
        pooled = fmaxf(pooled, part[s * OC + t]);

    __shared__ float shw[4][4];          // [warp][tc]
    #pragma unroll
    for (int tc = 0; tc < 4; tc++) {
        float v = pooled * fc1_w[tc * OC + t];
        #pragma unroll
        for (int off = 16; off > 0; off >>= 1)
            v += __shfl_down_sync(0xFFFFFFFFu, v, off);
        if (lane == 0) shw[warp][tc] = v;
    }
    __syncthreads();
    if (t < 4) {
        float s = shw[0][t] + shw[1][t] + shw[2][t] + shw[3][t];
        out[b * 4 + t] = s + fc1_b[t];
    }
}

// ---------------------------------------------------------------------------
extern "C" void kernel_launch(void* const* d_in, const int* in_sizes, int n_in,
                              void* d_out, int out_size) {
    const int*   tokens = (const int*)  d_in[0];
    const float* k1     = (const float*)d_in[1];
    const float* fc1w   = (const float*)d_in[2];
    const float* fc1b   = (const float*)d_in[3];
    float*       out    = (float*)d_out;

    transpose_kernel<<<(CW + 63) / 64, 256>>>(k1);     // 2344 blocks

    conv_kernel<<<dim3(NSUB / 8, BATCH), 256>>>(tokens);

    final_kernel<<<BATCH, 128>>>(fc1w, fc1b, out);
}